// round 2
// baseline (speedup 1.0000x reference)
#include <cuda_runtime.h>
#include <math.h>

#define B_SZ   32
#define NTOK   3136
#define DMODEL 384
#define HEADS  8
#define CDIM   48

// Scratch (static device globals — allocation-free rule)
__device__ float g_qkv[(size_t)3 * B_SZ * DMODEL * NTOK];   // [3][B][384][N]  462 MB
__device__ float g_rnorm[2 * B_SZ * DMODEL];                // [2][B][384]
__device__ float g_ctx[(size_t)B_SZ * NTOK * DMODEL];       // [B][N][D]      154 MB

// ---------------------------------------------------------------------------
// Kernel 1: qkv[b, e, n] = sum_d x[b,n,d] * w[e,d], written as [3][B][384][N]
// Tiles: BM=128 (e), BN=64 (n), BK=16. 256 threads, 8x4 per thread.
// ---------------------------------------------------------------------------
__global__ __launch_bounds__(256) void qkv_gemm(const float* __restrict__ x,
                                                const float* __restrict__ w) {
    __shared__ __align__(16) float As[16][128];
    __shared__ __align__(16) float Bs[16][64];

    const int b     = blockIdx.z;
    const int eBase = blockIdx.y * 128;
    const int nBase = blockIdx.x * 64;
    const float* xb = x + (size_t)b * NTOK * DMODEL;

    const int tid = threadIdx.x;
    const int tx  = tid & 15;   // n-sub
    const int ty  = tid >> 4;   // e-sub

    float acc[8][4];
#pragma unroll
    for (int i = 0; i < 8; i++)
#pragma unroll
        for (int j = 0; j < 4; j++) acc[i][j] = 0.f;

    for (int kb = 0; kb < DMODEL; kb += 16) {
        // load A (w): 128x16 = 512 float4, 2 per thread
#pragma unroll
        for (int r = 0; r < 2; r++) {
            int v    = tid + r * 256;
            int row  = v >> 2;
            int quad = v & 3;
            float4 t4 = *(const float4*)(w + (size_t)(eBase + row) * DMODEL + kb + quad * 4);
            As[quad * 4 + 0][row] = t4.x;
            As[quad * 4 + 1][row] = t4.y;
            As[quad * 4 + 2][row] = t4.z;
            As[quad * 4 + 3][row] = t4.w;
        }
        // load B (x): 64x16 = 256 float4, 1 per thread
        {
            int row  = tid >> 2;
            int quad = tid & 3;
            float4 t4 = *(const float4*)(xb + (size_t)(nBase + row) * DMODEL + kb + quad * 4);
            Bs[quad * 4 + 0][row] = t4.x;
            Bs[quad * 4 + 1][row] = t4.y;
            Bs[quad * 4 + 2][row] = t4.z;
            Bs[quad * 4 + 3][row] = t4.w;
        }
        __syncthreads();

#pragma unroll
        for (int k = 0; k < 16; k++) {
            float a[8], bb[4];
            *(float4*)(a)     = *(const float4*)&As[k][ty * 8];
            *(float4*)(a + 4) = *(const float4*)&As[k][ty * 8 + 4];
            *(float4*)(bb)    = *(const float4*)&Bs[k][tx * 4];
#pragma unroll
            for (int i = 0; i < 8; i++)
#pragma unroll
                for (int j = 0; j < 4; j++) acc[i][j] = fmaf(a[i], bb[j], acc[i][j]);
        }
        __syncthreads();
    }

#pragma unroll
    for (int i = 0; i < 8; i++) {
        int e    = eBase + ty * 8 + i;
        int part = e / DMODEL;
        int r    = e % DMODEL;
        float* dst = g_qkv + ((size_t)part * B_SZ + b) * DMODEL * NTOK
                   + (size_t)r * NTOK + nBase + tx * 4;
        *(float4*)dst = make_float4(acc[i][0], acc[i][1], acc[i][2], acc[i][3]);
    }
}

// ---------------------------------------------------------------------------
// Kernel 2: per-row (length 3136) inverse L2 norm for q and k
// ---------------------------------------------------------------------------
__global__ __launch_bounds__(256) void norm_kernel() {
    const int row  = blockIdx.x;                 // 0 .. 2*32*384-1
    const int part = row / (B_SZ * DMODEL);
    const int rr   = row % (B_SZ * DMODEL);
    const float4* p = (const float4*)(g_qkv + (size_t)part * B_SZ * DMODEL * NTOK
                                      + (size_t)rr * NTOK);
    const int tid = threadIdx.x;
    float s = 0.f;
    for (int i = tid; i < NTOK / 4; i += 256) {
        float4 v = p[i];
        s += v.x * v.x + v.y * v.y + v.z * v.z + v.w * v.w;
    }
#pragma unroll
    for (int off = 16; off; off >>= 1) s += __shfl_down_sync(0xFFFFFFFFu, s, off);
    __shared__ float ws[8];
    if ((tid & 31) == 0) ws[tid >> 5] = s;
    __syncthreads();
    if (tid == 0) {
        float t = 0.f;
#pragma unroll
        for (int i = 0; i < 8; i++) t += ws[i];
        g_rnorm[row] = 1.0f / fmaxf(sqrtf(t), 1e-12f);
    }
}

// ---------------------------------------------------------------------------
// Kernel 3: per (b,h): attn = softmax(qn·knT * temp), ctx = attn·v
// One block of 256 threads per (b,h). Streams N in chunks of 64.
// ---------------------------------------------------------------------------
__global__ __launch_bounds__(256) void attn_kernel(const float* __restrict__ temp) {
    const int bh = blockIdx.x;
    const int b  = bh >> 3;
    const int h  = bh & 7;

    const size_t PART = (size_t)B_SZ * DMODEL * NTOK;
    const float* qp = g_qkv + 0 * PART + ((size_t)b * DMODEL + h * CDIM) * NTOK;
    const float* kp = g_qkv + 1 * PART + ((size_t)b * DMODEL + h * CDIM) * NTOK;
    const float* vp = g_qkv + 2 * PART + ((size_t)b * DMODEL + h * CDIM) * NTOK;

    __shared__ float qs[48][65];
    __shared__ float ks[48][65];   // reused as v-chunk in phase 2
    __shared__ float attn[48][49];
    __shared__ float qinv[48], kinv[48];

    const int tid = threadIdx.x;
    if (tid < 48) {
        qinv[tid] = g_rnorm[b * DMODEL + h * CDIM + tid];
        kinv[tid] = g_rnorm[B_SZ * DMODEL + b * DMODEL + h * CDIM + tid];
    }

    const int tx = tid & 15;   // d group (3 cols)
    const int ty = tid >> 4;   // c group (3 rows)
    float acc[3][3];
#pragma unroll
    for (int i = 0; i < 3; i++)
#pragma unroll
        for (int j = 0; j < 3; j++) acc[i][j] = 0.f;

    // ---- phase 1: QK^T over N ----
    for (int n0 = 0; n0 < NTOK; n0 += 64) {
        __syncthreads();
#pragma unroll
        for (int r = 0; r < 3; r++) {
            int v   = tid + r * 256;      // float4 id, 768 total
            int row = v >> 4;
            int col = (v & 15) * 4;
            float4 tq = *(const float4*)(qp + (size_t)row * NTOK + n0 + col);
            qs[row][col + 0] = tq.x; qs[row][col + 1] = tq.y;
            qs[row][col + 2] = tq.z; qs[row][col + 3] = tq.w;
            float4 tk = *(const float4*)(kp + (size_t)row * NTOK + n0 + col);
            ks[row][col + 0] = tk.x; ks[row][col + 1] = tk.y;
            ks[row][col + 2] = tk.z; ks[row][col + 3] = tk.w;
        }
        __syncthreads();
#pragma unroll 8
        for (int kk = 0; kk < 64; kk++) {
            float a0 = qs[3 * ty + 0][kk];
            float a1 = qs[3 * ty + 1][kk];
            float a2 = qs[3 * ty + 2][kk];
            float b0 = ks[3 * tx + 0][kk];
            float b1 = ks[3 * tx + 1][kk];
            float b2 = ks[3 * tx + 2][kk];
            acc[0][0] = fmaf(a0, b0, acc[0][0]); acc[0][1] = fmaf(a0, b1, acc[0][1]); acc[0][2] = fmaf(a0, b2, acc[0][2]);
            acc[1][0] = fmaf(a1, b0, acc[1][0]); acc[1][1] = fmaf(a1, b1, acc[1][1]); acc[1][2] = fmaf(a1, b2, acc[1][2]);
            acc[2][0] = fmaf(a2, b0, acc[2][0]); acc[2][1] = fmaf(a2, b1, acc[2][1]); acc[2][2] = fmaf(a2, b2, acc[2][2]);
        }
    }

    __syncthreads();
    {
        const float tval = temp[h];
#pragma unroll
        for (int i = 0; i < 3; i++)
#pragma unroll
            for (int j = 0; j < 3; j++)
                attn[3 * ty + i][3 * tx + j] =
                    acc[i][j] * qinv[3 * ty + i] * kinv[3 * tx + j] * tval;
    }
    __syncthreads();

    // ---- softmax over d (rows of attn) ----
    if (tid < 48) {
        float m = -1e30f;
#pragma unroll
        for (int d = 0; d < 48; d++) m = fmaxf(m, attn[tid][d]);
        float s = 0.f;
#pragma unroll
        for (int d = 0; d < 48; d++) {
            float e = expf(attn[tid][d] - m);
            attn[tid][d] = e;
            s += e;
        }
        float inv = 1.0f / s;
#pragma unroll
        for (int d = 0; d < 48; d++) attn[tid][d] *= inv;
    }
    __syncthreads();

    // ---- phase 2: ctx = attn · v, streamed over N ----
    const int tx2 = tid & 63;   // n within chunk
    const int ty2 = tid >> 6;   // c base (0..3)
    float* dstBase = g_ctx + (size_t)b * NTOK * DMODEL + h * CDIM;

    for (int n0 = 0; n0 < NTOK; n0 += 64) {
        __syncthreads();
#pragma unroll
        for (int r = 0; r < 3; r++) {
            int v   = tid + r * 256;
            int row = v >> 4;
            int col = (v & 15) * 4;
            float4 tv = *(const float4*)(vp + (size_t)row * NTOK + n0 + col);
            ks[row][col + 0] = tv.x; ks[row][col + 1] = tv.y;
            ks[row][col + 2] = tv.z; ks[row][col + 3] = tv.w;
        }
        __syncthreads();

        float out[12];
#pragma unroll
        for (int i = 0; i < 12; i++) out[i] = 0.f;
#pragma unroll 8
        for (int d = 0; d < 48; d++) {
            float v = ks[d][tx2];
#pragma unroll
            for (int i = 0; i < 12; i++)
                out[i] = fmaf(attn[ty2 + 4 * i][d], v, out[i]);
        }
        // stage to smem for coalesced global write (c-fastest)
#pragma unroll
        for (int i = 0; i < 12; i++) qs[ty2 + 4 * i][tx2] = out[i];
        __syncthreads();
        for (int v = tid; v < 48 * 64; v += 256) {
            int c = v % 48;
            int n = v / 48;
            dstBase[(size_t)(n0 + n) * DMODEL + c] = qs[c][n];
        }
    }
}

// ---------------------------------------------------------------------------
// Kernel 4: y[bn, e] = sum_d ctx[bn, d] * proj_w[e, d] + bias[e]
// BM=128 (bn), BN=64 (e), BK=16
// ---------------------------------------------------------------------------
__global__ __launch_bounds__(256) void proj_gemm(const float* __restrict__ w,
                                                 const float* __restrict__ bias,
                                                 float* __restrict__ y) {
    __shared__ __align__(16) float As[16][128];
    __shared__ __align__(16) float Bs[16][64];

    const int bnBase = blockIdx.x * 128;
    const int eBase  = blockIdx.y * 64;

    const int tid = threadIdx.x;
    const int tx  = tid & 15;
    const int ty  = tid >> 4;

    float acc[8][4];
#pragma unroll
    for (int i = 0; i < 8; i++)
#pragma unroll
        for (int j = 0; j < 4; j++) acc[i][j] = 0.f;

    for (int kb = 0; kb < DMODEL; kb += 16) {
        // A = ctx rows
#pragma unroll
        for (int r = 0; r < 2; r++) {
            int v    = tid + r * 256;
            int row  = v >> 2;
            int quad = v & 3;
            float4 t4 = *(const float4*)(g_ctx + (size_t)(bnBase + row) * DMODEL + kb + quad * 4);
            As[quad * 4 + 0][row] = t4.x;
            As[quad * 4 + 1][row] = t4.y;
            As[quad * 4 + 2][row] = t4.z;
            As[quad * 4 + 3][row] = t4.w;
        }
        // B = proj_w rows
        {
            int row  = tid >> 2;
            int quad = tid & 3;
            float4 t4 = *(const float4*)(w + (size_t)(eBase + row) * DMODEL + kb + quad * 4);
            Bs[quad * 4 + 0][row] = t4.x;
            Bs[quad * 4 + 1][row] = t4.y;
            Bs[quad * 4 + 2][row] = t4.z;
            Bs[quad * 4 + 3][row] = t4.w;
        }
        __syncthreads();
#pragma unroll
        for (int k = 0; k < 16; k++) {
            float a[8], bb[4];
            *(float4*)(a)     = *(const float4*)&As[k][ty * 8];
            *(float4*)(a + 4) = *(const float4*)&As[k][ty * 8 + 4];
            *(float4*)(bb)    = *(const float4*)&Bs[k][tx * 4];
#pragma unroll
            for (int i = 0; i < 8; i++)
#pragma unroll
                for (int j = 0; j < 4; j++) acc[i][j] = fmaf(a[i], bb[j], acc[i][j]);
        }
        __syncthreads();
    }

#pragma unroll
    for (int i = 0; i < 8; i++) {
        int bn = bnBase + ty * 8 + i;
        int e0 = eBase + tx * 4;
        float4 bv = *(const float4*)(bias + e0);
        float4 o  = make_float4(acc[i][0] + bv.x, acc[i][1] + bv.y,
                                acc[i][2] + bv.z, acc[i][3] + bv.w);
        *(float4*)(y + (size_t)bn * DMODEL + e0) = o;
    }
}

// ---------------------------------------------------------------------------
extern "C" void kernel_launch(void* const* d_in, const int* in_sizes, int n_in,
                              void* d_out, int out_size) {
    const float* x      = (const float*)d_in[0];
    const float* qkv_w  = (const float*)d_in[1];
    const float* temp   = (const float*)d_in[2];
    const float* proj_w = (const float*)d_in[3];
    const float* proj_b = (const float*)d_in[4];
    float* y = (float*)d_out;

    qkv_gemm<<<dim3(NTOK / 64, (3 * DMODEL) / 128, B_SZ), 256>>>(x, qkv_w);
    norm_kernel<<<2 * B_SZ * DMODEL, 256>>>();
    attn_kernel<<<B_SZ * HEADS, 256>>>(temp);
    proj_gemm<<<dim3((B_SZ * NTOK) / 128, DMODEL / 64), 256>>>(proj_w, proj_b, y);
}

// round 3
// speedup vs baseline: 2.0005x; 2.0005x over previous
#include <cuda_runtime.h>
#include <math.h>
#include <stdint.h>

#define B_SZ   32
#define NTOK   3136
#define DMODEL 384
#define HEADS  8
#define CDIM   48
#define BM     128
#define BN     128
#define BKT    16

// Scratch (static device globals — allocation-free rule)
__device__ float g_qkv[(size_t)3 * B_SZ * DMODEL * NTOK];   // [3][B][384][N]
__device__ float g_rnorm[2 * B_SZ * DMODEL];                // [2][B][384]
__device__ float g_ctx[(size_t)B_SZ * NTOK * DMODEL];       // [B][N][D] bn-major
__device__ float g_attnp[7 * 256 * CDIM * CDIM];            // partial QK^T sums
__device__ float g_attn[256 * CDIM * CDIM];                 // softmaxed attn

__device__ __forceinline__ uint32_t f2tf32(float x) {
    uint32_t r; asm("cvt.rna.tf32.f32 %0, %1;" : "=r"(r) : "f"(x)); return r;
}

__device__ __forceinline__ void mma_tf32(float* d, const uint32_t* a, const uint32_t* b) {
    asm volatile(
        "mma.sync.aligned.m16n8k8.row.col.f32.tf32.tf32.f32 "
        "{%0,%1,%2,%3}, {%4,%5,%6,%7}, {%8,%9}, {%0,%1,%2,%3};\n"
        : "+f"(d[0]), "+f"(d[1]), "+f"(d[2]), "+f"(d[3])
        : "r"(a[0]), "r"(a[1]), "r"(a[2]), "r"(a[3]), "r"(b[0]), "r"(b[1]));
}

// ---------------------------------------------------------------------------
// Kernel 1: qkv GEMM (TF32 tensor cores)
// C[bn, e] = X[bn, :] . W[e, :]   (M=100352, N=1152, K=384)
// Output scattered to g_qkv[part][b][r][n] via smem staging.
// ---------------------------------------------------------------------------
__global__ __launch_bounds__(256) void qkv_mma(const float* __restrict__ x,
                                               const float* __restrict__ w) {
    __shared__ __align__(16) uint32_t As[BM][BKT + 4];   // stride 20
    __shared__ __align__(16) uint32_t Ws[BN][BKT + 4];
    __shared__ __align__(16) float stage[32][132];

    const int tid  = threadIdx.x;
    const int lane = tid & 31;
    const int warp = tid >> 5;
    const int gid  = lane >> 2;
    const int tig  = lane & 3;
    const int wm   = warp >> 2;   // 0..1
    const int wn   = warp & 3;    // 0..3

    const size_t mBase = (size_t)blockIdx.x * BM;   // over bn
    const int    eBase = blockIdx.y * BN;           // over e

    float acc[4][4][4];
#pragma unroll
    for (int i = 0; i < 4; i++)
#pragma unroll
        for (int j = 0; j < 4; j++)
#pragma unroll
            for (int r = 0; r < 4; r++) acc[i][j][r] = 0.f;

    for (int kb = 0; kb < DMODEL; kb += BKT) {
#pragma unroll
        for (int r = 0; r < 2; r++) {
            int v = tid + r * 256;
            int row = v >> 2, quad = v & 3;
            float4 t = *(const float4*)(x + (mBase + row) * DMODEL + kb + quad * 4);
            uint4 u = make_uint4(f2tf32(t.x), f2tf32(t.y), f2tf32(t.z), f2tf32(t.w));
            *(uint4*)&As[row][quad * 4] = u;
            float4 t2 = *(const float4*)(w + (size_t)(eBase + row) * DMODEL + kb + quad * 4);
            uint4 u2 = make_uint4(f2tf32(t2.x), f2tf32(t2.y), f2tf32(t2.z), f2tf32(t2.w));
            *(uint4*)&Ws[row][quad * 4] = u2;
        }
        __syncthreads();

#pragma unroll
        for (int ks = 0; ks < 2; ks++) {
            const int k0 = ks * 8;
            uint32_t af[4][4], bf[4][2];
#pragma unroll
            for (int i = 0; i < 4; i++) {
                int m = wm * 64 + i * 16;
                af[i][0] = As[m + gid][k0 + tig];
                af[i][1] = As[m + gid + 8][k0 + tig];
                af[i][2] = As[m + gid][k0 + tig + 4];
                af[i][3] = As[m + gid + 8][k0 + tig + 4];
            }
#pragma unroll
            for (int j = 0; j < 4; j++) {
                int n = wn * 32 + j * 8;
                bf[j][0] = Ws[n + gid][k0 + tig];
                bf[j][1] = Ws[n + gid][k0 + tig + 4];
            }
#pragma unroll
            for (int i = 0; i < 4; i++)
#pragma unroll
                for (int j = 0; j < 4; j++)
                    mma_tf32(acc[i][j], af[i], bf[j]);
        }
        __syncthreads();
    }

    // epilogue: 4 rounds of 32 e-cols, staged for coalesced [e][n] stores
    const size_t PART = (size_t)B_SZ * DMODEL * NTOK;
    for (int rnd = 0; rnd < 4; rnd++) {
        __syncthreads();
        if (wn == rnd) {
#pragma unroll
            for (int i = 0; i < 4; i++) {
                int m0 = wm * 64 + i * 16 + gid;
#pragma unroll
                for (int j = 0; j < 4; j++) {
                    int e0 = j * 8 + 2 * tig;
                    stage[e0][m0]         = acc[i][j][0];
                    stage[e0 + 1][m0]     = acc[i][j][1];
                    stage[e0][m0 + 8]     = acc[i][j][2];
                    stage[e0 + 1][m0 + 8] = acc[i][j][3];
                }
            }
        }
        __syncthreads();
        int tok4 = (tid & 31) * 4;
#pragma unroll
        for (int ii = 0; ii < 4; ii++) {
            int el = (tid >> 5) + 8 * ii;
            int eg = eBase + rnd * 32 + el;
            int part = eg / DMODEL, rr = eg % DMODEL;
            size_t bn = mBase + tok4;
            int b = (int)(bn / NTOK);
            int n = (int)(bn - (size_t)b * NTOK);
            float4 vv = *(float4*)&stage[el][tok4];
            *(float4*)(g_qkv + (size_t)part * PART + ((size_t)b * DMODEL + rr) * NTOK + n) = vv;
        }
    }
}

// ---------------------------------------------------------------------------
// Kernel 2: per-row inverse L2 norm for q and k
// ---------------------------------------------------------------------------
__global__ __launch_bounds__(256) void norm_kernel() {
    const int row  = blockIdx.x;
    const int part = row / (B_SZ * DMODEL);
    const int rr   = row % (B_SZ * DMODEL);
    const float4* p = (const float4*)(g_qkv + (size_t)part * B_SZ * DMODEL * NTOK
                                      + (size_t)rr * NTOK);
    const int tid = threadIdx.x;
    float s = 0.f;
    for (int i = tid; i < NTOK / 4; i += 256) {
        float4 v = p[i];
        s += v.x * v.x + v.y * v.y + v.z * v.z + v.w * v.w;
    }
#pragma unroll
    for (int off = 16; off; off >>= 1) s += __shfl_down_sync(0xFFFFFFFFu, s, off);
    __shared__ float ws[8];
    if ((tid & 31) == 0) ws[tid >> 5] = s;
    __syncthreads();
    if (tid == 0) {
        float t = 0.f;
#pragma unroll
        for (int i = 0; i < 8; i++) t += ws[i];
        g_rnorm[row] = 1.0f / fmaxf(sqrtf(t), 1e-12f);
    }
}

// ---------------------------------------------------------------------------
// Kernel 3a: partial QK^T: grid (7 chunks, 256 bh). Deterministic partials.
// ---------------------------------------------------------------------------
__global__ __launch_bounds__(256) void qk_partial() {
    const int chunk = blockIdx.x;     // 0..6, 448 tokens each
    const int bh    = blockIdx.y;
    const int b = bh >> 3, h = bh & 7;

    const size_t PART = (size_t)B_SZ * DMODEL * NTOK;
    const float* qp = g_qkv + ((size_t)b * DMODEL + h * CDIM) * NTOK;
    const float* kp = g_qkv + PART + ((size_t)b * DMODEL + h * CDIM) * NTOK;

    __shared__ float qs[48][65];
    __shared__ float ks[48][65];

    const int tid = threadIdx.x;
    const int tx = tid & 15;
    const int ty = tid >> 4;
    float acc[3][3];
#pragma unroll
    for (int i = 0; i < 3; i++)
#pragma unroll
        for (int j = 0; j < 3; j++) acc[i][j] = 0.f;

    const int nStart = chunk * 448;
    for (int n0 = nStart; n0 < nStart + 448; n0 += 64) {
        __syncthreads();
#pragma unroll
        for (int r = 0; r < 3; r++) {
            int v   = tid + r * 256;
            int row = v >> 4;
            int col = (v & 15) * 4;
            float4 tq = *(const float4*)(qp + (size_t)row * NTOK + n0 + col);
            qs[row][col + 0] = tq.x; qs[row][col + 1] = tq.y;
            qs[row][col + 2] = tq.z; qs[row][col + 3] = tq.w;
            float4 tk = *(const float4*)(kp + (size_t)row * NTOK + n0 + col);
            ks[row][col + 0] = tk.x; ks[row][col + 1] = tk.y;
            ks[row][col + 2] = tk.z; ks[row][col + 3] = tk.w;
        }
        __syncthreads();
#pragma unroll 8
        for (int kk = 0; kk < 64; kk++) {
            float a0 = qs[3 * ty + 0][kk];
            float a1 = qs[3 * ty + 1][kk];
            float a2 = qs[3 * ty + 2][kk];
            float b0 = ks[3 * tx + 0][kk];
            float b1 = ks[3 * tx + 1][kk];
            float b2 = ks[3 * tx + 2][kk];
            acc[0][0] = fmaf(a0, b0, acc[0][0]); acc[0][1] = fmaf(a0, b1, acc[0][1]); acc[0][2] = fmaf(a0, b2, acc[0][2]);
            acc[1][0] = fmaf(a1, b0, acc[1][0]); acc[1][1] = fmaf(a1, b1, acc[1][1]); acc[1][2] = fmaf(a1, b2, acc[1][2]);
            acc[2][0] = fmaf(a2, b0, acc[2][0]); acc[2][1] = fmaf(a2, b1, acc[2][1]); acc[2][2] = fmaf(a2, b2, acc[2][2]);
        }
    }

    float* dst = g_attnp + ((size_t)chunk * 256 + bh) * (CDIM * CDIM);
#pragma unroll
    for (int i = 0; i < 3; i++)
#pragma unroll
        for (int j = 0; j < 3; j++)
            dst[(3 * ty + i) * CDIM + 3 * tx + j] = acc[i][j];
}

// ---------------------------------------------------------------------------
// Kernel 3b: reduce partials, scale by norms+temperature, row softmax
// one block (64 threads) per bh; thread = one c-row
// ---------------------------------------------------------------------------
__global__ __launch_bounds__(64) void softmax_kernel(const float* __restrict__ temp) {
    const int bh = blockIdx.x;
    const int b = bh >> 3, h = bh & 7;
    const int tid = threadIdx.x;

    __shared__ float kinv[48];
    if (tid < 48) kinv[tid] = g_rnorm[B_SZ * DMODEL + b * DMODEL + h * CDIM + tid];
    __syncthreads();
    if (tid >= 48) return;

    const float qi = g_rnorm[b * DMODEL + h * CDIM + tid];
    const float tv = temp[h];
    const size_t base = (size_t)bh * (CDIM * CDIM) + (size_t)tid * CDIM;

    float r[48];
#pragma unroll
    for (int d = 0; d < 48; d++) {
        float s = 0.f;
#pragma unroll
        for (int p = 0; p < 7; p++)
            s += g_attnp[(size_t)p * 256 * CDIM * CDIM + base + d];
        r[d] = s * qi * kinv[d] * tv;
    }
    float m = -1e30f;
#pragma unroll
    for (int d = 0; d < 48; d++) m = fmaxf(m, r[d]);
    float s = 0.f;
#pragma unroll
    for (int d = 0; d < 48; d++) { r[d] = expf(r[d] - m); s += r[d]; }
    float inv = 1.0f / s;
#pragma unroll
    for (int d = 0; d < 48; d++) g_attn[base + d] = r[d] * inv;
}

// ---------------------------------------------------------------------------
// Kernel 3c: ctx = attn . v, parallel over (chunk, bh)
// ---------------------------------------------------------------------------
__global__ __launch_bounds__(256) void av_kernel() {
    const int chunk = blockIdx.x;
    const int bh    = blockIdx.y;
    const int b = bh >> 3, h = bh & 7;

    const size_t PART = (size_t)B_SZ * DMODEL * NTOK;
    const float* vp = g_qkv + 2 * PART + ((size_t)b * DMODEL + h * CDIM) * NTOK;

    __shared__ float vsm[48][65];
    __shared__ float attn[48][49];
    __shared__ float osm[48][65];

    const int tid = threadIdx.x;
    // load attn probs
    for (int v = tid; v < 48 * 48; v += 256)
        attn[v / 48][v % 48] = g_attn[(size_t)bh * CDIM * CDIM + v];

    const int tx2 = tid & 63;
    const int ty2 = tid >> 6;
    float* dstBase = g_ctx + (size_t)b * NTOK * DMODEL + h * CDIM;

    const int nStart = chunk * 448;
    for (int n0 = nStart; n0 < nStart + 448; n0 += 64) {
        __syncthreads();
#pragma unroll
        for (int r = 0; r < 3; r++) {
            int v   = tid + r * 256;
            int row = v >> 4;
            int col = (v & 15) * 4;
            float4 tv = *(const float4*)(vp + (size_t)row * NTOK + n0 + col);
            vsm[row][col + 0] = tv.x; vsm[row][col + 1] = tv.y;
            vsm[row][col + 2] = tv.z; vsm[row][col + 3] = tv.w;
        }
        __syncthreads();

        float out[12];
#pragma unroll
        for (int i = 0; i < 12; i++) out[i] = 0.f;
#pragma unroll 8
        for (int d = 0; d < 48; d++) {
            float v = vsm[d][tx2];
#pragma unroll
            for (int i = 0; i < 12; i++)
                out[i] = fmaf(attn[ty2 + 4 * i][d], v, out[i]);
        }
#pragma unroll
        for (int i = 0; i < 12; i++) osm[ty2 + 4 * i][tx2] = out[i];
        __syncthreads();
        for (int v = tid; v < 48 * 64; v += 256) {
            int c = v % 48;
            int n = v / 48;
            dstBase[(size_t)(n0 + n) * DMODEL + c] = osm[c][n];
        }
    }
}

// ---------------------------------------------------------------------------
// Kernel 4: proj GEMM (TF32): y[bn, e] = ctx[bn,:] . proj_w[e,:] + bias[e]
// ---------------------------------------------------------------------------
__global__ __launch_bounds__(256) void proj_mma(const float* __restrict__ w,
                                                const float* __restrict__ bias,
                                                float* __restrict__ y) {
    __shared__ __align__(16) uint32_t As[BM][BKT + 4];
    __shared__ __align__(16) uint32_t Ws[BN][BKT + 4];

    const int tid  = threadIdx.x;
    const int lane = tid & 31;
    const int warp = tid >> 5;
    const int gid  = lane >> 2;
    const int tig  = lane & 3;
    const int wm   = warp >> 2;
    const int wn   = warp & 3;

    const size_t mBase = (size_t)blockIdx.x * BM;
    const int    eBase = blockIdx.y * BN;

    float acc[4][4][4];
#pragma unroll
    for (int i = 0; i < 4; i++)
#pragma unroll
        for (int j = 0; j < 4; j++)
#pragma unroll
            for (int r = 0; r < 4; r++) acc[i][j][r] = 0.f;

    for (int kb = 0; kb < DMODEL; kb += BKT) {
#pragma unroll
        for (int r = 0; r < 2; r++) {
            int v = tid + r * 256;
            int row = v >> 2, quad = v & 3;
            float4 t = *(const float4*)(g_ctx + (mBase + row) * DMODEL + kb + quad * 4);
            uint4 u = make_uint4(f2tf32(t.x), f2tf32(t.y), f2tf32(t.z), f2tf32(t.w));
            *(uint4*)&As[row][quad * 4] = u;
            float4 t2 = *(const float4*)(w + (size_t)(eBase + row) * DMODEL + kb + quad * 4);
            uint4 u2 = make_uint4(f2tf32(t2.x), f2tf32(t2.y), f2tf32(t2.z), f2tf32(t2.w));
            *(uint4*)&Ws[row][quad * 4] = u2;
        }
        __syncthreads();

#pragma unroll
        for (int ks = 0; ks < 2; ks++) {
            const int k0 = ks * 8;
            uint32_t af[4][4], bf[4][2];
#pragma unroll
            for (int i = 0; i < 4; i++) {
                int m = wm * 64 + i * 16;
                af[i][0] = As[m + gid][k0 + tig];
                af[i][1] = As[m + gid + 8][k0 + tig];
                af[i][2] = As[m + gid][k0 + tig + 4];
                af[i][3] = As[m + gid + 8][k0 + tig + 4];
            }
#pragma unroll
            for (int j = 0; j < 4; j++) {
                int n = wn * 32 + j * 8;
                bf[j][0] = Ws[n + gid][k0 + tig];
                bf[j][1] = Ws[n + gid][k0 + tig + 4];
            }
#pragma unroll
            for (int i = 0; i < 4; i++)
#pragma unroll
                for (int j = 0; j < 4; j++)
                    mma_tf32(acc[i][j], af[i], bf[j]);
        }
        __syncthreads();
    }

#pragma unroll
    for (int i = 0; i < 4; i++) {
        size_t bn0 = mBase + wm * 64 + i * 16 + gid;
#pragma unroll
        for (int j = 0; j < 4; j++) {
            int e = eBase + wn * 32 + j * 8 + 2 * tig;
            float2 b2 = *(const float2*)(bias + e);
            float2 o0 = make_float2(acc[i][j][0] + b2.x, acc[i][j][1] + b2.y);
            float2 o1 = make_float2(acc[i][j][2] + b2.x, acc[i][j][3] + b2.y);
            *(float2*)(y + bn0 * DMODEL + e)       = o0;
            *(float2*)(y + (bn0 + 8) * DMODEL + e) = o1;
        }
    }
}

// ---------------------------------------------------------------------------
extern "C" void kernel_launch(void* const* d_in, const int* in_sizes, int n_in,
                              void* d_out, int out_size) {
    const float* x      = (const float*)d_in[0];
    const float* qkv_w  = (const float*)d_in[1];
    const float* temp   = (const float*)d_in[2];
    const float* proj_w = (const float*)d_in[3];
    const float* proj_b = (const float*)d_in[4];
    float* y = (float*)d_out;

    qkv_mma<<<dim3((B_SZ * NTOK) / BM, (3 * DMODEL) / BN), 256>>>(x, qkv_w);
    norm_kernel<<<2 * B_SZ * DMODEL, 256>>>();
    qk_partial<<<dim3(7, B_SZ * HEADS), 256>>>();
    softmax_kernel<<<B_SZ * HEADS, 64>>>(temp);
    av_kernel<<<dim3(7, B_SZ * HEADS), 256>>>();
    proj_mma<<<dim3((B_SZ * NTOK) / BM, DMODEL / BN), 256>>>(proj_w, proj_b, y);
}

// round 4
// speedup vs baseline: 2.2151x; 1.1073x over previous
#include <cuda_runtime.h>
#include <math.h>
#include <stdint.h>

#define B_SZ   32
#define NTOK   3136
#define DMODEL 384
#define HEADS  8
#define CDIM   48
#define BM     128
#define BN     128
#define BKT    16
#define KITERS (DMODEL / BKT)

// Scratch (static device globals — allocation-free rule)
__device__ float g_qkv[(size_t)3 * B_SZ * DMODEL * NTOK];   // [3][B][384][N]
__device__ float g_rnorm[2 * B_SZ * DMODEL];                // [2][B][384]
__device__ float g_ctx[(size_t)B_SZ * NTOK * DMODEL];       // [B][N][D] bn-major
__device__ float g_attnp[7 * 256 * CDIM * CDIM];            // partial QK^T sums
__device__ float g_attn[256 * CDIM * CDIM];                 // softmaxed attn

__device__ __forceinline__ uint32_t f2tf32(float x) {
    uint32_t r; asm("cvt.rna.tf32.f32 %0, %1;" : "=r"(r) : "f"(x)); return r;
}

__device__ __forceinline__ uint4 cvt4(float4 t) {
    return make_uint4(f2tf32(t.x), f2tf32(t.y), f2tf32(t.z), f2tf32(t.w));
}

__device__ __forceinline__ void mma_tf32(float* d, const uint32_t* a, const uint32_t* b) {
    asm volatile(
        "mma.sync.aligned.m16n8k8.row.col.f32.tf32.tf32.f32 "
        "{%0,%1,%2,%3}, {%4,%5,%6,%7}, {%8,%9}, {%0,%1,%2,%3};\n"
        : "+f"(d[0]), "+f"(d[1]), "+f"(d[2]), "+f"(d[3])
        : "r"(a[0]), "r"(a[1]), "r"(a[2]), "r"(a[3]), "r"(b[0]), "r"(b[1]));
}

// ---------------------------------------------------------------------------
// Kernel 1: qkv GEMM (TF32), double-buffered, L2-friendly grid order.
// grid.x = e-tile (9, fastest -> wave shares x slice in L2), grid.y = bn-tile.
// ---------------------------------------------------------------------------
__global__ __launch_bounds__(256, 2) void qkv_mma(const float* __restrict__ x,
                                                  const float* __restrict__ w) {
    __shared__ __align__(16) uint32_t As[2][BM][BKT + 4];
    __shared__ __align__(16) uint32_t Ws[2][BN][BKT + 4];

    const int tid  = threadIdx.x;
    const int lane = tid & 31;
    const int warp = tid >> 5;
    const int gid  = lane >> 2;
    const int tig  = lane & 3;
    const int wm   = warp >> 2;
    const int wn   = warp & 3;

    const size_t mBase = (size_t)blockIdx.y * BM;   // over bn
    const int    eBase = blockIdx.x * BN;           // over e

    // per-thread load slots: rows tid>>2 and 64+(tid>>2), quad = tid&3
    const int rowL = tid >> 2;
    const int quad = tid & 3;
    const float* xp0 = x + (mBase + rowL) * DMODEL + quad * 4;
    const float* xp1 = x + (mBase + rowL + 64) * DMODEL + quad * 4;
    const float* wp0 = w + (size_t)(eBase + rowL) * DMODEL + quad * 4;
    const float* wp1 = w + (size_t)(eBase + rowL + 64) * DMODEL + quad * 4;

    float acc[4][4][4];
#pragma unroll
    for (int i = 0; i < 4; i++)
#pragma unroll
        for (int j = 0; j < 4; j++)
#pragma unroll
            for (int r = 0; r < 4; r++) acc[i][j][r] = 0.f;

    float4 px0 = *(const float4*)(xp0);
    float4 px1 = *(const float4*)(xp1);
    float4 pw0 = *(const float4*)(wp0);
    float4 pw1 = *(const float4*)(wp1);
    *(uint4*)&As[0][rowL][quad * 4]      = cvt4(px0);
    *(uint4*)&As[0][rowL + 64][quad * 4] = cvt4(px1);
    *(uint4*)&Ws[0][rowL][quad * 4]      = cvt4(pw0);
    *(uint4*)&Ws[0][rowL + 64][quad * 4] = cvt4(pw1);
    __syncthreads();

    for (int kt = 0; kt < KITERS; kt++) {
        const int cur = kt & 1;
        if (kt + 1 < KITERS) {
            const int kb = (kt + 1) * BKT;
            px0 = *(const float4*)(xp0 + kb);
            px1 = *(const float4*)(xp1 + kb);
            pw0 = *(const float4*)(wp0 + kb);
            pw1 = *(const float4*)(wp1 + kb);
        }
#pragma unroll
        for (int ks = 0; ks < 2; ks++) {
            const int k0 = ks * 8;
            uint32_t af[4][4], bf[4][2];
#pragma unroll
            for (int i = 0; i < 4; i++) {
                int m = wm * 64 + i * 16;
                af[i][0] = As[cur][m + gid][k0 + tig];
                af[i][1] = As[cur][m + gid + 8][k0 + tig];
                af[i][2] = As[cur][m + gid][k0 + tig + 4];
                af[i][3] = As[cur][m + gid + 8][k0 + tig + 4];
            }
#pragma unroll
            for (int j = 0; j < 4; j++) {
                int n = wn * 32 + j * 8;
                bf[j][0] = Ws[cur][n + gid][k0 + tig];
                bf[j][1] = Ws[cur][n + gid][k0 + tig + 4];
            }
#pragma unroll
            for (int i = 0; i < 4; i++)
#pragma unroll
                for (int j = 0; j < 4; j++)
                    mma_tf32(acc[i][j], af[i], bf[j]);
        }
        if (kt + 1 < KITERS) {
            const int nxt = (kt + 1) & 1;
            *(uint4*)&As[nxt][rowL][quad * 4]      = cvt4(px0);
            *(uint4*)&As[nxt][rowL + 64][quad * 4] = cvt4(px1);
            *(uint4*)&Ws[nxt][rowL][quad * 4]      = cvt4(pw0);
            *(uint4*)&Ws[nxt][rowL + 64][quad * 4] = cvt4(pw1);
        }
        __syncthreads();
    }

    // epilogue: stage aliased over As (compute done); 4 rounds of 32 e-cols
    float (*stage)[132] = (float(*)[132]) & As[0][0][0];
    const size_t PART = (size_t)B_SZ * DMODEL * NTOK;
    for (int rnd = 0; rnd < 4; rnd++) {
        __syncthreads();
        if (wn == rnd) {
#pragma unroll
            for (int i = 0; i < 4; i++) {
                int m0 = wm * 64 + i * 16 + gid;
#pragma unroll
                for (int j = 0; j < 4; j++) {
                    int e0 = j * 8 + 2 * tig;
                    stage[e0][m0]         = acc[i][j][0];
                    stage[e0 + 1][m0]     = acc[i][j][1];
                    stage[e0][m0 + 8]     = acc[i][j][2];
                    stage[e0 + 1][m0 + 8] = acc[i][j][3];
                }
            }
        }
        __syncthreads();
        int tok4 = (tid & 31) * 4;
#pragma unroll
        for (int ii = 0; ii < 4; ii++) {
            int el = (tid >> 5) + 8 * ii;
            int eg = eBase + rnd * 32 + el;
            int part = eg / DMODEL, rr = eg % DMODEL;
            size_t bn = mBase + tok4;
            int b = (int)(bn / NTOK);
            int n = (int)(bn - (size_t)b * NTOK);
            float4 vv = *(float4*)&stage[el][tok4];
            *(float4*)(g_qkv + (size_t)part * PART + ((size_t)b * DMODEL + rr) * NTOK + n) = vv;
        }
    }
}

// ---------------------------------------------------------------------------
// Kernel 2: per-row inverse L2 norm for q and k
// ---------------------------------------------------------------------------
__global__ __launch_bounds__(256) void norm_kernel() {
    const int row  = blockIdx.x;
    const int part = row / (B_SZ * DMODEL);
    const int rr   = row % (B_SZ * DMODEL);
    const float4* p = (const float4*)(g_qkv + (size_t)part * B_SZ * DMODEL * NTOK
                                      + (size_t)rr * NTOK);
    const int tid = threadIdx.x;
    float s = 0.f;
    for (int i = tid; i < NTOK / 4; i += 256) {
        float4 v = p[i];
        s += v.x * v.x + v.y * v.y + v.z * v.z + v.w * v.w;
    }
#pragma unroll
    for (int off = 16; off; off >>= 1) s += __shfl_down_sync(0xFFFFFFFFu, s, off);
    __shared__ float ws[8];
    if ((tid & 31) == 0) ws[tid >> 5] = s;
    __syncthreads();
    if (tid == 0) {
        float t = 0.f;
#pragma unroll
        for (int i = 0; i < 8; i++) t += ws[i];
        g_rnorm[row] = 1.0f / fmaxf(sqrtf(t), 1e-12f);
    }
}

// ---------------------------------------------------------------------------
// Kernel 3a: partial QK^T: grid (7 chunks, 256 bh). Deterministic partials.
// ---------------------------------------------------------------------------
__global__ __launch_bounds__(256) void qk_partial() {
    const int chunk = blockIdx.x;     // 0..6, 448 tokens each
    const int bh    = blockIdx.y;
    const int b = bh >> 3, h = bh & 7;

    const size_t PART = (size_t)B_SZ * DMODEL * NTOK;
    const float* qp = g_qkv + ((size_t)b * DMODEL + h * CDIM) * NTOK;
    const float* kp = g_qkv + PART + ((size_t)b * DMODEL + h * CDIM) * NTOK;

    __shared__ float qs[48][65];
    __shared__ float ks[48][65];

    const int tid = threadIdx.x;
    const int tx = tid & 15;
    const int ty = tid >> 4;
    float acc[3][3];
#pragma unroll
    for (int i = 0; i < 3; i++)
#pragma unroll
        for (int j = 0; j < 3; j++) acc[i][j] = 0.f;

    const int nStart = chunk * 448;
    for (int n0 = nStart; n0 < nStart + 448; n0 += 64) {
        __syncthreads();
#pragma unroll
        for (int r = 0; r < 3; r++) {
            int v   = tid + r * 256;
            int row = v >> 4;
            int col = (v & 15) * 4;
            float4 tq = *(const float4*)(qp + (size_t)row * NTOK + n0 + col);
            qs[row][col + 0] = tq.x; qs[row][col + 1] = tq.y;
            qs[row][col + 2] = tq.z; qs[row][col + 3] = tq.w;
            float4 tk = *(const float4*)(kp + (size_t)row * NTOK + n0 + col);
            ks[row][col + 0] = tk.x; ks[row][col + 1] = tk.y;
            ks[row][col + 2] = tk.z; ks[row][col + 3] = tk.w;
        }
        __syncthreads();
#pragma unroll 8
        for (int kk = 0; kk < 64; kk++) {
            float a0 = qs[3 * ty + 0][kk];
            float a1 = qs[3 * ty + 1][kk];
            float a2 = qs[3 * ty + 2][kk];
            float b0 = ks[3 * tx + 0][kk];
            float b1 = ks[3 * tx + 1][kk];
            float b2 = ks[3 * tx + 2][kk];
            acc[0][0] = fmaf(a0, b0, acc[0][0]); acc[0][1] = fmaf(a0, b1, acc[0][1]); acc[0][2] = fmaf(a0, b2, acc[0][2]);
            acc[1][0] = fmaf(a1, b0, acc[1][0]); acc[1][1] = fmaf(a1, b1, acc[1][1]); acc[1][2] = fmaf(a1, b2, acc[1][2]);
            acc[2][0] = fmaf(a2, b0, acc[2][0]); acc[2][1] = fmaf(a2, b1, acc[2][1]); acc[2][2] = fmaf(a2, b2, acc[2][2]);
        }
    }

    float* dst = g_attnp + ((size_t)chunk * 256 + bh) * (CDIM * CDIM);
#pragma unroll
    for (int i = 0; i < 3; i++)
#pragma unroll
        for (int j = 0; j < 3; j++)
            dst[(3 * ty + i) * CDIM + 3 * tx + j] = acc[i][j];
}

// ---------------------------------------------------------------------------
// Kernel 3b: reduce partials, scale by norms+temperature, row softmax
// ---------------------------------------------------------------------------
__global__ __launch_bounds__(64) void softmax_kernel(const float* __restrict__ temp) {
    const int bh = blockIdx.x;
    const int b = bh >> 3, h = bh & 7;
    const int tid = threadIdx.x;

    __shared__ float kinv[48];
    if (tid < 48) kinv[tid] = g_rnorm[B_SZ * DMODEL + b * DMODEL + h * CDIM + tid];
    __syncthreads();
    if (tid >= 48) return;

    const float qi = g_rnorm[b * DMODEL + h * CDIM + tid];
    const float tv = temp[h];
    const size_t base = (size_t)bh * (CDIM * CDIM) + (size_t)tid * CDIM;

    float r[48];
#pragma unroll
    for (int d = 0; d < 48; d++) {
        float s = 0.f;
#pragma unroll
        for (int p = 0; p < 7; p++)
            s += g_attnp[(size_t)p * 256 * CDIM * CDIM + base + d];
        r[d] = s * qi * kinv[d] * tv;
    }
    float m = -1e30f;
#pragma unroll
    for (int d = 0; d < 48; d++) m = fmaxf(m, r[d]);
    float s = 0.f;
#pragma unroll
    for (int d = 0; d < 48; d++) { r[d] = expf(r[d] - m); s += r[d]; }
    float inv = 1.0f / s;
#pragma unroll
    for (int d = 0; d < 48; d++) g_attn[base + d] = r[d] * inv;
}

// ---------------------------------------------------------------------------
// Kernel 3c: ctx = attn . v, parallel over (chunk, bh)
// ---------------------------------------------------------------------------
__global__ __launch_bounds__(256) void av_kernel() {
    const int chunk = blockIdx.x;
    const int bh    = blockIdx.y;
    const int b = bh >> 3, h = bh & 7;

    const size_t PART = (size_t)B_SZ * DMODEL * NTOK;
    const float* vp = g_qkv + 2 * PART + ((size_t)b * DMODEL + h * CDIM) * NTOK;

    __shared__ float vsm[48][65];
    __shared__ float attn[48][49];
    __shared__ float osm[48][65];

    const int tid = threadIdx.x;
    for (int v = tid; v < 48 * 48; v += 256)
        attn[v / 48][v % 48] = g_attn[(size_t)bh * CDIM * CDIM + v];

    const int tx2 = tid & 63;
    const int ty2 = tid >> 6;
    float* dstBase = g_ctx + (size_t)b * NTOK * DMODEL + h * CDIM;

    const int nStart = chunk * 448;
    for (int n0 = nStart; n0 < nStart + 448; n0 += 64) {
        __syncthreads();
#pragma unroll
        for (int r = 0; r < 3; r++) {
            int v   = tid + r * 256;
            int row = v >> 4;
            int col = (v & 15) * 4;
            float4 tv = *(const float4*)(vp + (size_t)row * NTOK + n0 + col);
            vsm[row][col + 0] = tv.x; vsm[row][col + 1] = tv.y;
            vsm[row][col + 2] = tv.z; vsm[row][col + 3] = tv.w;
        }
        __syncthreads();

        float out[12];
#pragma unroll
        for (int i = 0; i < 12; i++) out[i] = 0.f;
#pragma unroll 8
        for (int d = 0; d < 48; d++) {
            float v = vsm[d][tx2];
#pragma unroll
            for (int i = 0; i < 12; i++)
                out[i] = fmaf(attn[ty2 + 4 * i][d], v, out[i]);
        }
#pragma unroll
        for (int i = 0; i < 12; i++) osm[ty2 + 4 * i][tx2] = out[i];
        __syncthreads();
        for (int v = tid; v < 48 * 64; v += 256) {
            int c = v % 48;
            int n = v / 48;
            dstBase[(size_t)(n0 + n) * DMODEL + c] = osm[c][n];
        }
    }
}

// ---------------------------------------------------------------------------
// Kernel 4: proj GEMM (TF32), double-buffered, L2-friendly grid order.
// grid.x = e-tile (3, fastest), grid.y = bn-tile (784).
// ---------------------------------------------------------------------------
__global__ __launch_bounds__(256, 2) void proj_mma(const float* __restrict__ w,
                                                   const float* __restrict__ bias,
                                                   float* __restrict__ y) {
    __shared__ __align__(16) uint32_t As[2][BM][BKT + 4];
    __shared__ __align__(16) uint32_t Ws[2][BN][BKT + 4];

    const int tid  = threadIdx.x;
    const int lane = tid & 31;
    const int warp = tid >> 5;
    const int gid  = lane >> 2;
    const int tig  = lane & 3;
    const int wm   = warp >> 2;
    const int wn   = warp & 3;

    const size_t mBase = (size_t)blockIdx.y * BM;
    const int    eBase = blockIdx.x * BN;

    const int rowL = tid >> 2;
    const int quad = tid & 3;
    const float* ap0 = g_ctx + (mBase + rowL) * DMODEL + quad * 4;
    const float* ap1 = g_ctx + (mBase + rowL + 64) * DMODEL + quad * 4;
    const float* wp0 = w + (size_t)(eBase + rowL) * DMODEL + quad * 4;
    const float* wp1 = w + (size_t)(eBase + rowL + 64) * DMODEL + quad * 4;

    float acc[4][4][4];
#pragma unroll
    for (int i = 0; i < 4; i++)
#pragma unroll
        for (int j = 0; j < 4; j++)
#pragma unroll
            for (int r = 0; r < 4; r++) acc[i][j][r] = 0.f;

    float4 pa0 = *(const float4*)(ap0);
    float4 pa1 = *(const float4*)(ap1);
    float4 pw0 = *(const float4*)(wp0);
    float4 pw1 = *(const float4*)(wp1);
    *(uint4*)&As[0][rowL][quad * 4]      = cvt4(pa0);
    *(uint4*)&As[0][rowL + 64][quad * 4] = cvt4(pa1);
    *(uint4*)&Ws[0][rowL][quad * 4]      = cvt4(pw0);
    *(uint4*)&Ws[0][rowL + 64][quad * 4] = cvt4(pw1);
    __syncthreads();

    for (int kt = 0; kt < KITERS; kt++) {
        const int cur = kt & 1;
        if (kt + 1 < KITERS) {
            const int kb = (kt + 1) * BKT;
            pa0 = *(const float4*)(ap0 + kb);
            pa1 = *(const float4*)(ap1 + kb);
            pw0 = *(const float4*)(wp0 + kb);
            pw1 = *(const float4*)(wp1 + kb);
        }
#pragma unroll
        for (int ks = 0; ks < 2; ks++) {
            const int k0 = ks * 8;
            uint32_t af[4][4], bf[4][2];
#pragma unroll
            for (int i = 0; i < 4; i++) {
                int m = wm * 64 + i * 16;
                af[i][0] = As[cur][m + gid][k0 + tig];
                af[i][1] = As[cur][m + gid + 8][k0 + tig];
                af[i][2] = As[cur][m + gid][k0 + tig + 4];
                af[i][3] = As[cur][m + gid + 8][k0 + tig + 4];
            }
#pragma unroll
            for (int j = 0; j < 4; j++) {
                int n = wn * 32 + j * 8;
                bf[j][0] = Ws[cur][n + gid][k0 + tig];
                bf[j][1] = Ws[cur][n + gid][k0 + tig + 4];
            }
#pragma unroll
            for (int i = 0; i < 4; i++)
#pragma unroll
                for (int j = 0; j < 4; j++)
                    mma_tf32(acc[i][j], af[i], bf[j]);
        }
        if (kt + 1 < KITERS) {
            const int nxt = (kt + 1) & 1;
            *(uint4*)&As[nxt][rowL][quad * 4]      = cvt4(pa0);
            *(uint4*)&As[nxt][rowL + 64][quad * 4] = cvt4(pa1);
            *(uint4*)&Ws[nxt][rowL][quad * 4]      = cvt4(pw0);
            *(uint4*)&Ws[nxt][rowL + 64][quad * 4] = cvt4(pw1);
        }
        __syncthreads();
    }

#pragma unroll
    for (int i = 0; i < 4; i++) {
        size_t bn0 = mBase + wm * 64 + i * 16 + gid;
#pragma unroll
        for (int j = 0; j < 4; j++) {
            int e = eBase + wn * 32 + j * 8 + 2 * tig;
            float2 b2 = *(const float2*)(bias + e);
            float2 o0 = make_float2(acc[i][j][0] + b2.x, acc[i][j][1] + b2.y);
            float2 o1 = make_float2(acc[i][j][2] + b2.x, acc[i][j][3] + b2.y);
            *(float2*)(y + bn0 * DMODEL + e)       = o0;
            *(float2*)(y + (bn0 + 8) * DMODEL + e) = o1;
        }
    }
}

// ---------------------------------------------------------------------------
extern "C" void kernel_launch(void* const* d_in, const int* in_sizes, int n_in,
                              void* d_out, int out_size) {
    const float* x      = (const float*)d_in[0];
    const float* qkv_w  = (const float*)d_in[1];
    const float* temp   = (const float*)d_in[2];
    const float* proj_w = (const float*)d_in[3];
    const float* proj_b = (const float*)d_in[4];
    float* y = (float*)d_out;

    qkv_mma<<<dim3((3 * DMODEL) / BN, (B_SZ * NTOK) / BM), 256>>>(x, qkv_w);
    norm_kernel<<<2 * B_SZ * DMODEL, 256>>>();
    qk_partial<<<dim3(7, B_SZ * HEADS), 256>>>();
    softmax_kernel<<<B_SZ * HEADS, 64>>>(temp);
    av_kernel<<<dim3(7, B_SZ * HEADS), 256>>>();
    proj_mma<<<dim3(DMODEL / BN, (B_SZ * NTOK) / BM), 256>>>(proj_w, proj_b, y);
}